// round 11
// baseline (speedup 1.0000x reference)
#include <cuda_runtime.h>

#define N_IN  700
#define NN    2068     // N_HIDDEN + N_OUT
#define NOUT  20
#define BB    256
#define TT    100
#define TAU   0.6f
#define VTH   1.0f

#define ROWS  (BB * TT)        // 25600 rows of the ff GEMM

// Eigen gebp kc blocking: k_cache = min((l1-ksub)/kdiv, 320) rounded to mult of 8
// -> kc = 320 for any l1 >= ~21KB. Panels are combined as C += panel (sequential
// separately-rounded fp32 adds); within a panel: single ascending fused-madd chain.
#define KC        320
#define KC_ITERS  (KC / 8)     // 40 tile-iterations of BK=8 per panel

// Scratch (device globals: allocation-free rule)
__device__ float g_ff[(size_t)TT * BB * NN];   // [T][B][N]  ~212 MB
__device__ float g_mem[BB * NN];
__device__ float g_spkA[BB * NN];
__device__ float g_spkB[BB * NN];

// ---------------------------------------------------------------------------
__global__ void zero_state_kernel() {
    int i = blockIdx.x * blockDim.x + threadIdx.x;
    int total = BB * NN;
    if (i < total) {
        g_mem[i]  = 0.0f;
        g_spkA[i] = 0.0f;
    }
}

// ---------------------------------------------------------------------------
// Phase 1: ff[t][b][n] = sum_i x[b][t][i] * W1[n][i]
// K = 700 -> Eigen panels [0,320) [320,640) [640,700):
//   tot = ((P0 + P1) + P2), each P an ascending FMA chain from 0.
// ---------------------------------------------------------------------------
__global__ __launch_bounds__(256)
void ff_gemm_kernel(const float* __restrict__ X, const float* __restrict__ W1) {
    __shared__ float As[8][64];
    __shared__ float Bs[8][64];

    const int col0 = blockIdx.x * 64;   // n
    const int row0 = blockIdx.y * 64;   // r = b*TT + t
    const int tid  = threadIdx.x;
    const int tx   = tid & 15;          // n-dim
    const int ty   = tid >> 4;          // r-dim

    float acc[4][4] = {};   // current panel accumulator
    float tot[4][4] = {};   // running C += panel total

    const int nk = (N_IN + 7) / 8;      // 88
    int panel_ctr = 0;
    for (int kk = 0; kk < nk; kk++) {
        const int k0 = kk * 8;
        if (tid < 128) {
            int m  = tid >> 1;              // 0..63
            int kq = (tid & 1) * 4;         // 0 or 4
            int gk = k0 + kq;
            int gr = row0 + m;
            float4 v;
            if (gk + 4 <= N_IN) {
                v = *(const float4*)&X[(size_t)gr * N_IN + gk];
            } else {
                v.x = (gk + 0 < N_IN) ? X[(size_t)gr * N_IN + gk + 0] : 0.f;
                v.y = (gk + 1 < N_IN) ? X[(size_t)gr * N_IN + gk + 1] : 0.f;
                v.z = (gk + 2 < N_IN) ? X[(size_t)gr * N_IN + gk + 2] : 0.f;
                v.w = (gk + 3 < N_IN) ? X[(size_t)gr * N_IN + gk + 3] : 0.f;
            }
            As[kq + 0][m] = v.x; As[kq + 1][m] = v.y;
            As[kq + 2][m] = v.z; As[kq + 3][m] = v.w;
        } else {
            int e  = tid - 128;
            int n  = e >> 1;                // 0..63
            int kq = (e & 1) * 4;
            int gk = k0 + kq;
            int gn = col0 + n;
            float4 v = {0.f, 0.f, 0.f, 0.f};
            if (gn < NN) {
                if (gk + 4 <= N_IN) {
                    v = *(const float4*)&W1[(size_t)gn * N_IN + gk];
                } else {
                    v.x = (gk + 0 < N_IN) ? W1[(size_t)gn * N_IN + gk + 0] : 0.f;
                    v.y = (gk + 1 < N_IN) ? W1[(size_t)gn * N_IN + gk + 1] : 0.f;
                    v.z = (gk + 2 < N_IN) ? W1[(size_t)gn * N_IN + gk + 2] : 0.f;
                    v.w = (gk + 3 < N_IN) ? W1[(size_t)gn * N_IN + gk + 3] : 0.f;
                }
            }
            Bs[kq + 0][n] = v.x; Bs[kq + 1][n] = v.y;
            Bs[kq + 2][n] = v.z; Bs[kq + 3][n] = v.w;
        }
        __syncthreads();

        #pragma unroll
        for (int k = 0; k < 8; k++) {
            float4 a = *(const float4*)&As[k][ty * 4];
            float4 b = *(const float4*)&Bs[k][tx * 4];
            acc[0][0] = __fmaf_rn(a.x, b.x, acc[0][0]); acc[0][1] = __fmaf_rn(a.x, b.y, acc[0][1]);
            acc[0][2] = __fmaf_rn(a.x, b.z, acc[0][2]); acc[0][3] = __fmaf_rn(a.x, b.w, acc[0][3]);
            acc[1][0] = __fmaf_rn(a.y, b.x, acc[1][0]); acc[1][1] = __fmaf_rn(a.y, b.y, acc[1][1]);
            acc[1][2] = __fmaf_rn(a.y, b.z, acc[1][2]); acc[1][3] = __fmaf_rn(a.y, b.w, acc[1][3]);
            acc[2][0] = __fmaf_rn(a.z, b.x, acc[2][0]); acc[2][1] = __fmaf_rn(a.z, b.y, acc[2][1]);
            acc[2][2] = __fmaf_rn(a.z, b.z, acc[2][2]); acc[2][3] = __fmaf_rn(a.z, b.w, acc[2][3]);
            acc[3][0] = __fmaf_rn(a.w, b.x, acc[3][0]); acc[3][1] = __fmaf_rn(a.w, b.y, acc[3][1]);
            acc[3][2] = __fmaf_rn(a.w, b.z, acc[3][2]); acc[3][3] = __fmaf_rn(a.w, b.w, acc[3][3]);
        }
        __syncthreads();

        // Close an Eigen kc-panel: C += panel (separately rounded), reset panel acc
        if (++panel_ctr == KC_ITERS) {
            panel_ctr = 0;
            #pragma unroll
            for (int i = 0; i < 4; i++)
                #pragma unroll
                for (int j = 0; j < 4; j++) {
                    tot[i][j] = __fadd_rn(tot[i][j], acc[i][j]);
                    acc[i][j] = 0.0f;
                }
        }
    }
    // tail panel
    #pragma unroll
    for (int i = 0; i < 4; i++)
        #pragma unroll
        for (int j = 0; j < 4; j++)
            tot[i][j] = __fadd_rn(tot[i][j], acc[i][j]);

    #pragma unroll
    for (int i = 0; i < 4; i++) {
        int r = row0 + ty * 4 + i;
        int b = r / TT;
        int t = r % TT;
        size_t base = (size_t)t * BB * NN + (size_t)b * NN;
        #pragma unroll
        for (int j = 0; j < 4; j++) {
            int n = col0 + tx * 4 + j;
            if (n < NN) g_ff[base + n] = tot[i][j];
        }
    }
}

// ---------------------------------------------------------------------------
// Phase 2 step: cur[b][n] = ff_t[b][n] + sum_j spk_in[b][j] * Wrec[j][n]
// K = 2068 -> Eigen kc=320 panels: [0,320) ... [1920,2068), folded sequentially
// tot = (...((P0+P1)+P2)...)+P6, each add separately rounded.
// LIF epilogue: each elementwise HLO op individually rounded.
// ---------------------------------------------------------------------------
__global__ __launch_bounds__(256)
void step_kernel(const float* __restrict__ Wrec, float* __restrict__ out, int t) {
    const float* __restrict__ spk_in  = (t & 1) ? g_spkB : g_spkA;
    float* __restrict__       spk_out = (t & 1) ? g_spkA : g_spkB;
    const float* __restrict__ ff_t    = g_ff + (size_t)t * BB * NN;

    __shared__ float As[8][64];
    __shared__ float Bs[8][64];

    const int col0 = blockIdx.x * 64;   // n
    const int row0 = blockIdx.y * 64;   // b
    const int tid  = threadIdx.x;
    const int tx   = tid & 15;
    const int ty   = tid >> 4;

    float acc[4][4] = {};   // current panel accumulator
    float tot[4][4] = {};   // running C += panel total

    const int nk = (NN + 7) / 8;       // 259
    int panel_ctr = 0;
    for (int kk = 0; kk < nk; kk++) {
        const int k0 = kk * 8;
        if (tid < 128) {
            int m  = tid >> 1;
            int kq = (tid & 1) * 4;
            int gk = k0 + kq;
            int gb = row0 + m;
            float4 v;
            if (gk + 4 <= NN) {
                v = *(const float4*)&spk_in[(size_t)gb * NN + gk];
            } else {
                v.x = (gk + 0 < NN) ? spk_in[(size_t)gb * NN + gk + 0] : 0.f;
                v.y = (gk + 1 < NN) ? spk_in[(size_t)gb * NN + gk + 1] : 0.f;
                v.z = (gk + 2 < NN) ? spk_in[(size_t)gb * NN + gk + 2] : 0.f;
                v.w = (gk + 3 < NN) ? spk_in[(size_t)gb * NN + gk + 3] : 0.f;
            }
            As[kq + 0][m] = v.x; As[kq + 1][m] = v.y;
            As[kq + 2][m] = v.z; As[kq + 3][m] = v.w;
        } else {
            int e  = tid - 128;             // 0..127
            int k  = e >> 4;                // 0..7
            int n4 = (e & 15) * 4;          // 0..60
            int gk = k0 + k;
            int gn = col0 + n4;
            float4 v = {0.f, 0.f, 0.f, 0.f};
            if (gk < NN) {
                if (gn + 4 <= NN) {
                    v = *(const float4*)&Wrec[(size_t)gk * NN + gn];
                } else {
                    v.x = (gn + 0 < NN) ? Wrec[(size_t)gk * NN + gn + 0] : 0.f;
                    v.y = (gn + 1 < NN) ? Wrec[(size_t)gk * NN + gn + 1] : 0.f;
                    v.z = (gn + 2 < NN) ? Wrec[(size_t)gk * NN + gn + 2] : 0.f;
                    v.w = (gn + 3 < NN) ? Wrec[(size_t)gk * NN + gn + 3] : 0.f;
                }
            }
            Bs[k][n4 + 0] = v.x; Bs[k][n4 + 1] = v.y;
            Bs[k][n4 + 2] = v.z; Bs[k][n4 + 3] = v.w;
        }
        __syncthreads();

        #pragma unroll
        for (int k = 0; k < 8; k++) {
            float4 a = *(const float4*)&As[k][ty * 4];
            float4 b = *(const float4*)&Bs[k][tx * 4];
            acc[0][0] = __fmaf_rn(a.x, b.x, acc[0][0]); acc[0][1] = __fmaf_rn(a.x, b.y, acc[0][1]);
            acc[0][2] = __fmaf_rn(a.x, b.z, acc[0][2]); acc[0][3] = __fmaf_rn(a.x, b.w, acc[0][3]);
            acc[1][0] = __fmaf_rn(a.y, b.x, acc[1][0]); acc[1][1] = __fmaf_rn(a.y, b.y, acc[1][1]);
            acc[1][2] = __fmaf_rn(a.y, b.z, acc[1][2]); acc[1][3] = __fmaf_rn(a.y, b.w, acc[1][3]);
            acc[2][0] = __fmaf_rn(a.z, b.x, acc[2][0]); acc[2][1] = __fmaf_rn(a.z, b.y, acc[2][1]);
            acc[2][2] = __fmaf_rn(a.z, b.z, acc[2][2]); acc[2][3] = __fmaf_rn(a.z, b.w, acc[2][3]);
            acc[3][0] = __fmaf_rn(a.w, b.x, acc[3][0]); acc[3][1] = __fmaf_rn(a.w, b.y, acc[3][1]);
            acc[3][2] = __fmaf_rn(a.w, b.z, acc[3][2]); acc[3][3] = __fmaf_rn(a.w, b.w, acc[3][3]);
        }
        __syncthreads();

        // Close an Eigen kc-panel: C += panel, reset panel acc
        if (++panel_ctr == KC_ITERS) {
            panel_ctr = 0;
            #pragma unroll
            for (int i = 0; i < 4; i++)
                #pragma unroll
                for (int j = 0; j < 4; j++) {
                    tot[i][j] = __fadd_rn(tot[i][j], acc[i][j]);
                    acc[i][j] = 0.0f;
                }
        }
    }
    // tail panel [1920, 2068)
    #pragma unroll
    for (int i = 0; i < 4; i++)
        #pragma unroll
        for (int j = 0; j < 4; j++)
            tot[i][j] = __fadd_rn(tot[i][j], acc[i][j]);

    // LIF update + spike + output — each HLO op individually rounded
    #pragma unroll
    for (int i = 0; i < 4; i++) {
        int b = row0 + ty * 4 + i;
        size_t base = (size_t)b * NN;
        #pragma unroll
        for (int j = 0; j < 4; j++) {
            int n = col0 + tx * 4 + j;
            if (n < NN) {
                float gemm = tot[i][j];
                float ffv = ff_t[base + n];
                float m0  = g_mem[base + n];
                float sp0 = spk_in[base + n];
                float cur = __fadd_rn(ffv, gemm);               // ff + gemm
                float t1  = __fmul_rn(TAU, m0);                 // tau*mem
                float t2  = __fsub_rn(1.0f, sp0);               // 1-spk (exact)
                float t3  = __fmul_rn(t1, t2);                  // product
                float mn  = __fadd_rn(t3, cur);                 // + cur
                float sn  = (mn >= VTH) ? 1.0f : 0.0f;
                g_mem[base + n]   = mn;
                spk_out[base + n] = sn;
                if (n >= NN - NOUT) {
                    out[(size_t)b * TT * NOUT + (size_t)t * NOUT + (n - (NN - NOUT))] = sn;
                }
            }
        }
    }
}

// ---------------------------------------------------------------------------
extern "C" void kernel_launch(void* const* d_in, const int* in_sizes, int n_in,
                              void* d_out, int out_size) {
    // Identify inputs by element count (robust to ordering):
    //   x:     256*100*700 = 17,920,000
    //   W_fc1: 2068*700    =  1,447,600
    //   W_rec: 2068*2068   =  4,276,624
    const float* x  = nullptr;
    const float* W1 = nullptr;
    const float* Wr = nullptr;
    for (int i = 0; i < n_in; i++) {
        if (in_sizes[i] == ROWS * N_IN)      x  = (const float*)d_in[i];
        else if (in_sizes[i] == NN * N_IN)   W1 = (const float*)d_in[i];
        else if (in_sizes[i] == NN * NN)     Wr = (const float*)d_in[i];
    }
    float* out = (float*)d_out;                // [256, 100, 20]

    {
        int total = BB * NN;
        int threads = 256;
        int blocks = (total + threads - 1) / threads;
        zero_state_kernel<<<blocks, threads>>>();
    }

    {
        dim3 grid((NN + 63) / 64, ROWS / 64);  // (33, 400)
        ff_gemm_kernel<<<grid, 256>>>(x, W1);
    }

    {
        dim3 grid((NN + 63) / 64, BB / 64);    // (33, 4)
        for (int t = 0; t < TT; t++) {
            step_kernel<<<grid, 256>>>(Wr, out, t);
        }
    }
}

// round 13
// speedup vs baseline: 2.6216x; 2.6216x over previous
#include <cuda_runtime.h>

#define N_IN  700
#define NN    2068     // N_HIDDEN + N_OUT
#define NOUT  20
#define BB    256
#define TT    100
#define TAU   0.6f
#define VTH   1.0f

#define ROWS  (BB * TT)        // 25600 rows of the ff GEMM

// Eigen gebp kc blocking (confirmed bit-exact in R11): kc = 320.
// Panels: p0..p5 = [320p, 320p+320), p6 = [1920, 2068)
#define KC        320
#define KC_ITERS  (KC / 8)
#define NPANEL    7

// Scratch (device globals: allocation-free rule)
__device__ float g_ff[(size_t)TT * BB * NN];   // [T][B][N]  ~212 MB
__device__ float g_mem[BB * NN];
__device__ float g_spkA[BB * NN];
__device__ float g_spkB[BB * NN];
__device__ int   g_idx[BB * NPANEL * KC];      // ordered spiking indices per (b, panel)
__device__ int   g_cnt[BB * NPANEL];           // counts per (b, panel)

// ---------------------------------------------------------------------------
__global__ void zero_state_kernel() {
    int i = blockIdx.x * blockDim.x + threadIdx.x;
    int total = BB * NN;
    if (i < total) {
        g_mem[i]  = 0.0f;
        g_spkA[i] = 0.0f;
    }
}

// ---------------------------------------------------------------------------
// Phase 1: ff[t][b][n] = sum_i x[b][t][i] * W1[n][i]
// K = 700 -> Eigen panels [0,320) [320,640) [640,700):
//   tot = ((P0 + P1) + P2), each P an ascending FMA chain from 0.
// (unchanged from R11 — bit-exact verified)
// ---------------------------------------------------------------------------
__global__ __launch_bounds__(256)
void ff_gemm_kernel(const float* __restrict__ X, const float* __restrict__ W1) {
    __shared__ float As[8][64];
    __shared__ float Bs[8][64];

    const int col0 = blockIdx.x * 64;   // n
    const int row0 = blockIdx.y * 64;   // r = b*TT + t
    const int tid  = threadIdx.x;
    const int tx   = tid & 15;          // n-dim
    const int ty   = tid >> 4;          // r-dim

    float acc[4][4] = {};   // current panel accumulator
    float tot[4][4] = {};   // running C += panel total

    const int nk = (N_IN + 7) / 8;      // 88
    int panel_ctr = 0;
    for (int kk = 0; kk < nk; kk++) {
        const int k0 = kk * 8;
        if (tid < 128) {
            int m  = tid >> 1;              // 0..63
            int kq = (tid & 1) * 4;         // 0 or 4
            int gk = k0 + kq;
            int gr = row0 + m;
            float4 v;
            if (gk + 4 <= N_IN) {
                v = *(const float4*)&X[(size_t)gr * N_IN + gk];
            } else {
                v.x = (gk + 0 < N_IN) ? X[(size_t)gr * N_IN + gk + 0] : 0.f;
                v.y = (gk + 1 < N_IN) ? X[(size_t)gr * N_IN + gk + 1] : 0.f;
                v.z = (gk + 2 < N_IN) ? X[(size_t)gr * N_IN + gk + 2] : 0.f;
                v.w = (gk + 3 < N_IN) ? X[(size_t)gr * N_IN + gk + 3] : 0.f;
            }
            As[kq + 0][m] = v.x; As[kq + 1][m] = v.y;
            As[kq + 2][m] = v.z; As[kq + 3][m] = v.w;
        } else {
            int e  = tid - 128;
            int n  = e >> 1;                // 0..63
            int kq = (e & 1) * 4;
            int gk = k0 + kq;
            int gn = col0 + n;
            float4 v = {0.f, 0.f, 0.f, 0.f};
            if (gn < NN) {
                if (gk + 4 <= N_IN) {
                    v = *(const float4*)&W1[(size_t)gn * N_IN + gk];
                } else {
                    v.x = (gk + 0 < N_IN) ? W1[(size_t)gn * N_IN + gk + 0] : 0.f;
                    v.y = (gk + 1 < N_IN) ? W1[(size_t)gn * N_IN + gk + 1] : 0.f;
                    v.z = (gk + 2 < N_IN) ? W1[(size_t)gn * N_IN + gk + 2] : 0.f;
                    v.w = (gk + 3 < N_IN) ? W1[(size_t)gn * N_IN + gk + 3] : 0.f;
                }
            }
            Bs[kq + 0][n] = v.x; Bs[kq + 1][n] = v.y;
            Bs[kq + 2][n] = v.z; Bs[kq + 3][n] = v.w;
        }
        __syncthreads();

        #pragma unroll
        for (int k = 0; k < 8; k++) {
            float4 a = *(const float4*)&As[k][ty * 4];
            float4 b = *(const float4*)&Bs[k][tx * 4];
            acc[0][0] = __fmaf_rn(a.x, b.x, acc[0][0]); acc[0][1] = __fmaf_rn(a.x, b.y, acc[0][1]);
            acc[0][2] = __fmaf_rn(a.x, b.z, acc[0][2]); acc[0][3] = __fmaf_rn(a.x, b.w, acc[0][3]);
            acc[1][0] = __fmaf_rn(a.y, b.x, acc[1][0]); acc[1][1] = __fmaf_rn(a.y, b.y, acc[1][1]);
            acc[1][2] = __fmaf_rn(a.y, b.z, acc[1][2]); acc[1][3] = __fmaf_rn(a.y, b.w, acc[1][3]);
            acc[2][0] = __fmaf_rn(a.z, b.x, acc[2][0]); acc[2][1] = __fmaf_rn(a.z, b.y, acc[2][1]);
            acc[2][2] = __fmaf_rn(a.z, b.z, acc[2][2]); acc[2][3] = __fmaf_rn(a.z, b.w, acc[2][3]);
            acc[3][0] = __fmaf_rn(a.w, b.x, acc[3][0]); acc[3][1] = __fmaf_rn(a.w, b.y, acc[3][1]);
            acc[3][2] = __fmaf_rn(a.w, b.z, acc[3][2]); acc[3][3] = __fmaf_rn(a.w, b.w, acc[3][3]);
        }
        __syncthreads();

        if (++panel_ctr == KC_ITERS) {
            panel_ctr = 0;
            #pragma unroll
            for (int i = 0; i < 4; i++)
                #pragma unroll
                for (int j = 0; j < 4; j++) {
                    tot[i][j] = __fadd_rn(tot[i][j], acc[i][j]);
                    acc[i][j] = 0.0f;
                }
        }
    }
    #pragma unroll
    for (int i = 0; i < 4; i++)
        #pragma unroll
        for (int j = 0; j < 4; j++)
            tot[i][j] = __fadd_rn(tot[i][j], acc[i][j]);

    #pragma unroll
    for (int i = 0; i < 4; i++) {
        int r = row0 + ty * 4 + i;
        int b = r / TT;
        int t = r % TT;
        size_t base = (size_t)t * BB * NN + (size_t)b * NN;
        #pragma unroll
        for (int j = 0; j < 4; j++) {
            int n = col0 + tx * 4 + j;
            if (n < NN) g_ff[base + n] = tot[i][j];
        }
    }
}

// ---------------------------------------------------------------------------
// Spike compaction: one warp per batch row. Builds ordered (ascending j)
// index lists per (b, panel). Panel boundaries (multiples of 320) are
// multiples of 32, so a 32-wide chunk never straddles a panel.
// ---------------------------------------------------------------------------
__global__ __launch_bounds__(32)
void compact_kernel(int t) {
    const int b    = blockIdx.x;
    const int lane = threadIdx.x;
    const float* __restrict__ spk = ((t & 1) ? g_spkB : g_spkA) + (size_t)b * NN;

    int cnt = 0;
    for (int j0 = 0; j0 < NN; j0 += 32) {
        if (j0 > 0 && (j0 % KC) == 0) {
            if (lane == 0) g_cnt[b * NPANEL + (j0 / KC) - 1] = cnt;
            cnt = 0;
        }
        int p = j0 / KC; if (p > 6) p = 6;
        int j = j0 + lane;
        float s = (j < NN) ? spk[j] : 0.0f;
        unsigned m = __ballot_sync(0xffffffffu, s != 0.0f);
        int pre = __popc(m & ((1u << lane) - 1u));
        if (s != 0.0f) g_idx[(b * NPANEL + p) * KC + cnt + pre] = j;
        cnt += __popc(m);
    }
    if (lane == 0) g_cnt[b * NPANEL + 6] = cnt;
}

// ---------------------------------------------------------------------------
// Sparse step: cur[b][n] = ff + sum over spiking j (ascending, kc=320 panels)
// of Wrec[j][n]. Bit-exact vs the dense FMA chain because spk in {0,1}:
//   fma(0,w,acc) == acc (exact), fma(1,w,acc) == rn(acc+w).
// Each thread owns 4 contiguous columns; LIF epilogue fused.
// Grid (5 chunks of 512 cols, 256 batch), 128 threads.
// ---------------------------------------------------------------------------
__global__ __launch_bounds__(128)
void sparse_step_kernel(const float* __restrict__ Wrec, float* __restrict__ out, int t) {
    const int b    = blockIdx.y;
    const int col0 = blockIdx.x * 512 + threadIdx.x * 4;
    if (col0 >= NN) return;

    const float* __restrict__ spk_in  = (t & 1) ? g_spkB : g_spkA;
    float* __restrict__       spk_out = (t & 1) ? g_spkA : g_spkB;

    float4 tot = {0.f, 0.f, 0.f, 0.f};

    #pragma unroll 1
    for (int p = 0; p < NPANEL; p++) {
        const int cnt = g_cnt[b * NPANEL + p];
        const int* __restrict__ lst = &g_idx[(b * NPANEL + p) * KC];
        float4 acc = {0.f, 0.f, 0.f, 0.f};
        #pragma unroll 4
        for (int i = 0; i < cnt; i++) {
            int j = lst[i];
            float4 w = *(const float4*)&Wrec[(size_t)j * NN + col0];
            acc.x = __fadd_rn(acc.x, w.x);
            acc.y = __fadd_rn(acc.y, w.y);
            acc.z = __fadd_rn(acc.z, w.z);
            acc.w = __fadd_rn(acc.w, w.w);
        }
        tot.x = __fadd_rn(tot.x, acc.x);
        tot.y = __fadd_rn(tot.y, acc.y);
        tot.z = __fadd_rn(tot.z, acc.z);
        tot.w = __fadd_rn(tot.w, acc.w);
    }

    // LIF epilogue — each HLO op individually rounded (unchanged semantics)
    const size_t base = (size_t)b * NN + col0;
    float4 ffv = *(const float4*)&g_ff[(size_t)t * BB * NN + base];
    float4 m0  = *(const float4*)&g_mem[base];
    float4 s0  = *(const float4*)&spk_in[base];

    float4 mn, sn;
    {
        float cur, t1, t2, t3;
        cur = __fadd_rn(ffv.x, tot.x); t1 = __fmul_rn(TAU, m0.x); t2 = __fsub_rn(1.0f, s0.x);
        t3 = __fmul_rn(t1, t2); mn.x = __fadd_rn(t3, cur); sn.x = (mn.x >= VTH) ? 1.0f : 0.0f;
        cur = __fadd_rn(ffv.y, tot.y); t1 = __fmul_rn(TAU, m0.y); t2 = __fsub_rn(1.0f, s0.y);
        t3 = __fmul_rn(t1, t2); mn.y = __fadd_rn(t3, cur); sn.y = (mn.y >= VTH) ? 1.0f : 0.0f;
        cur = __fadd_rn(ffv.z, tot.z); t1 = __fmul_rn(TAU, m0.z); t2 = __fsub_rn(1.0f, s0.z);
        t3 = __fmul_rn(t1, t2); mn.z = __fadd_rn(t3, cur); sn.z = (mn.z >= VTH) ? 1.0f : 0.0f;
        cur = __fadd_rn(ffv.w, tot.w); t1 = __fmul_rn(TAU, m0.w); t2 = __fsub_rn(1.0f, s0.w);
        t3 = __fmul_rn(t1, t2); mn.w = __fadd_rn(t3, cur); sn.w = (mn.w >= VTH) ? 1.0f : 0.0f;
    }

    *(float4*)&g_mem[base]   = mn;
    *(float4*)&spk_out[base] = sn;

    if (col0 >= NN - NOUT) {
        // out[b][t][c], c = col0 - 2048; row stride 20 floats (80B, 16B-aligned)
        *(float4*)&out[((size_t)b * TT + t) * NOUT + (col0 - (NN - NOUT))] = sn;
    }
}

// ---------------------------------------------------------------------------
extern "C" void kernel_launch(void* const* d_in, const int* in_sizes, int n_in,
                              void* d_out, int out_size) {
    // Identify inputs by element count (robust to ordering)
    const float* x  = nullptr;
    const float* W1 = nullptr;
    const float* Wr = nullptr;
    for (int i = 0; i < n_in; i++) {
        if (in_sizes[i] == ROWS * N_IN)      x  = (const float*)d_in[i];
        else if (in_sizes[i] == NN * N_IN)   W1 = (const float*)d_in[i];
        else if (in_sizes[i] == NN * NN)     Wr = (const float*)d_in[i];
    }
    float* out = (float*)d_out;                // [256, 100, 20]

    {
        int total = BB * NN;
        int threads = 256;
        int blocks = (total + threads - 1) / threads;
        zero_state_kernel<<<blocks, threads>>>();
    }

    {
        dim3 grid((NN + 63) / 64, ROWS / 64);  // (33, 400)
        ff_gemm_kernel<<<grid, 256>>>(x, W1);
    }

    {
        dim3 sgrid(5, BB);                     // 5 column-chunks x 256 batches
        for (int t = 0; t < TT; t++) {
            compact_kernel<<<BB, 32>>>(t);
            sparse_step_kernel<<<sgrid, 128>>>(Wr, out, t);
        }
    }
}

// round 15
// speedup vs baseline: 2.7938x; 1.0657x over previous
#include <cuda_runtime.h>

#define N_IN  700
#define NN    2068     // N_HIDDEN + N_OUT
#define NOUT  20
#define BB    256
#define TT    100
#define TAU   0.6f
#define VTH   1.0f

#define ROWS  (BB * TT)        // 25600 rows of the ff GEMM

// Eigen gebp kc blocking (confirmed bit-exact): kc = 320.
#define KC        320
#define NPANEL    7

// ff GEMM tiling
#define BM 128
#define BN 128
#define BK 16
#define FF_NK 44               // ceil(700/16) -> k padded to 704 with zeros

// Scratch (device globals: allocation-free rule)
__device__ float g_ff[(size_t)TT * BB * NN];   // [T][B][N]  ~212 MB
__device__ float g_mem[BB * NN];
__device__ float g_spkA[BB * NN];
__device__ float g_spkB[BB * NN];
__device__ int   g_idx[BB * NPANEL * KC];      // ordered spiking indices per (b, panel)
__device__ int   g_cnt[BB * NPANEL];           // counts per (b, panel)

// ---------------------------------------------------------------------------
__global__ void zero_state_kernel() {
    int i = blockIdx.x * blockDim.x + threadIdx.x;
    int total = BB * NN;
    if (i < total) {
        g_mem[i]  = 0.0f;
        g_spkA[i] = 0.0f;
    }
}

// ---------------------------------------------------------------------------
// Phase 1: ff[t][b][n] = sum_i x[b][t][i] * W1[n][i]     (GEMM-NT)
// Per-element: strictly ascending-k FMA chain, panel breaks after k=320, 640:
//   tot = ((P0 + P1) + P2)  with separately-rounded adds  (Eigen gebp kc=320).
// 128x128 tile, BK=16, 256 threads, 8x8 microtile, double-buffered smem,
// register-staged global loads (one __syncthreads per k-tile).
// ---------------------------------------------------------------------------
__global__ __launch_bounds__(256, 1)
void ff_gemm_kernel(const float* __restrict__ X, const float* __restrict__ W1) {
    __shared__ float As[2][BK][BM];
    __shared__ float Bs[2][BK][BN];

    const int col0 = blockIdx.x * BN;   // n
    const int row0 = blockIdx.y * BM;   // r = b*TT + t
    const int tid  = threadIdx.x;
    const int tx   = tid & 15;          // n-dim
    const int ty   = tid >> 4;          // r-dim

    // load mapping: each thread stages 2 float4 of A and 2 of B
    const int lrow = tid & 127;         // tile row (A) / tile col-index (B)
    const int lkq  = (tid >> 7) * 4;    // 0 or 4; second load at +8

    float4 stA0, stA1, stB0, stB1;

    // ---- stage tile kk=0 ----
    {
        const int k0 = 0;
        const int gr = row0 + lrow;
        const int gn = col0 + lrow;
        #pragma unroll
        for (int s = 0; s < 2; s++) {
            int kq = lkq + s * 8;
            int gk = k0 + kq;
            float4 va = {0.f,0.f,0.f,0.f}, vb = {0.f,0.f,0.f,0.f};
            if (gk + 4 <= N_IN) {
                va = *(const float4*)&X[(size_t)gr * N_IN + gk];
                if (gn < NN) vb = *(const float4*)&W1[(size_t)gn * N_IN + gk];
            } else {
                if (gk + 0 < N_IN) { va.x = X[(size_t)gr * N_IN + gk + 0]; if (gn < NN) vb.x = W1[(size_t)gn * N_IN + gk + 0]; }
                if (gk + 1 < N_IN) { va.y = X[(size_t)gr * N_IN + gk + 1]; if (gn < NN) vb.y = W1[(size_t)gn * N_IN + gk + 1]; }
                if (gk + 2 < N_IN) { va.z = X[(size_t)gr * N_IN + gk + 2]; if (gn < NN) vb.z = W1[(size_t)gn * N_IN + gk + 2]; }
                if (gk + 3 < N_IN) { va.w = X[(size_t)gr * N_IN + gk + 3]; if (gn < NN) vb.w = W1[(size_t)gn * N_IN + gk + 3]; }
            }
            As[0][kq + 0][lrow] = va.x; As[0][kq + 1][lrow] = va.y;
            As[0][kq + 2][lrow] = va.z; As[0][kq + 3][lrow] = va.w;
            Bs[0][kq + 0][lrow] = vb.x; Bs[0][kq + 1][lrow] = vb.y;
            Bs[0][kq + 2][lrow] = vb.z; Bs[0][kq + 3][lrow] = vb.w;
        }
    }
    __syncthreads();

    float acc[8][8] = {};   // current panel accumulator
    float tot[8][8] = {};   // running C += panel total

    int buf = 0;
    for (int kk = 0; kk < FF_NK; kk++) {
        // ---- stage tile kk+1 into registers (overlaps with compute) ----
        const bool have_next = (kk + 1 < FF_NK);
        if (have_next) {
            const int k0 = (kk + 1) * BK;
            const int gr = row0 + lrow;
            const int gn = col0 + lrow;
            {
                int gk = k0 + lkq;
                float4 va = {0.f,0.f,0.f,0.f}, vb = {0.f,0.f,0.f,0.f};
                if (gk + 4 <= N_IN) {
                    va = *(const float4*)&X[(size_t)gr * N_IN + gk];
                    if (gn < NN) vb = *(const float4*)&W1[(size_t)gn * N_IN + gk];
                } else {
                    if (gk + 0 < N_IN) { va.x = X[(size_t)gr * N_IN + gk + 0]; if (gn < NN) vb.x = W1[(size_t)gn * N_IN + gk + 0]; }
                    if (gk + 1 < N_IN) { va.y = X[(size_t)gr * N_IN + gk + 1]; if (gn < NN) vb.y = W1[(size_t)gn * N_IN + gk + 1]; }
                    if (gk + 2 < N_IN) { va.z = X[(size_t)gr * N_IN + gk + 2]; if (gn < NN) vb.z = W1[(size_t)gn * N_IN + gk + 2]; }
                    if (gk + 3 < N_IN) { va.w = X[(size_t)gr * N_IN + gk + 3]; if (gn < NN) vb.w = W1[(size_t)gn * N_IN + gk + 3]; }
                }
                stA0 = va; stB0 = vb;
            }
            {
                int gk = k0 + lkq + 8;
                float4 va = {0.f,0.f,0.f,0.f}, vb = {0.f,0.f,0.f,0.f};
                if (gk + 4 <= N_IN) {
                    va = *(const float4*)&X[(size_t)gr * N_IN + gk];
                    if (gn < NN) vb = *(const float4*)&W1[(size_t)gn * N_IN + gk];
                } else {
                    if (gk + 0 < N_IN) { va.x = X[(size_t)gr * N_IN + gk + 0]; if (gn < NN) vb.x = W1[(size_t)gn * N_IN + gk + 0]; }
                    if (gk + 1 < N_IN) { va.y = X[(size_t)gr * N_IN + gk + 1]; if (gn < NN) vb.y = W1[(size_t)gn * N_IN + gk + 1]; }
                    if (gk + 2 < N_IN) { va.z = X[(size_t)gr * N_IN + gk + 2]; if (gn < NN) vb.z = W1[(size_t)gn * N_IN + gk + 2]; }
                    if (gk + 3 < N_IN) { va.w = X[(size_t)gr * N_IN + gk + 3]; if (gn < NN) vb.w = W1[(size_t)gn * N_IN + gk + 3]; }
                }
                stA1 = va; stB1 = vb;
            }
        }

        // ---- compute 16 k-steps from smem[buf] ----
        #pragma unroll
        for (int k = 0; k < BK; k++) {
            float4 a0 = *(const float4*)&As[buf][k][ty * 4];
            float4 a1 = *(const float4*)&As[buf][k][64 + ty * 4];
            float4 b0 = *(const float4*)&Bs[buf][k][tx * 4];
            float4 b1 = *(const float4*)&Bs[buf][k][64 + tx * 4];
            float ar[8] = {a0.x, a0.y, a0.z, a0.w, a1.x, a1.y, a1.z, a1.w};
            float br[8] = {b0.x, b0.y, b0.z, b0.w, b1.x, b1.y, b1.z, b1.w};
            #pragma unroll
            for (int i = 0; i < 8; i++)
                #pragma unroll
                for (int j = 0; j < 8; j++)
                    acc[i][j] = __fmaf_rn(ar[i], br[j], acc[i][j]);
        }

        // ---- store staged tile into the other buffer ----
        if (have_next) {
            int nb = buf ^ 1;
            As[nb][lkq + 0][lrow] = stA0.x; As[nb][lkq + 1][lrow] = stA0.y;
            As[nb][lkq + 2][lrow] = stA0.z; As[nb][lkq + 3][lrow] = stA0.w;
            As[nb][lkq + 8][lrow] = stA1.x; As[nb][lkq + 9][lrow] = stA1.y;
            As[nb][lkq +10][lrow] = stA1.z; As[nb][lkq +11][lrow] = stA1.w;
            Bs[nb][lkq + 0][lrow] = stB0.x; Bs[nb][lkq + 1][lrow] = stB0.y;
            Bs[nb][lkq + 2][lrow] = stB0.z; Bs[nb][lkq + 3][lrow] = stB0.w;
            Bs[nb][lkq + 8][lrow] = stB1.x; Bs[nb][lkq + 9][lrow] = stB1.y;
            Bs[nb][lkq +10][lrow] = stB1.z; Bs[nb][lkq +11][lrow] = stB1.w;
            __syncthreads();
            buf = nb;
        }

        // ---- Eigen kc-panel boundaries: after k = 320 (kk==19), 640 (kk==39) ----
        if (kk == (KC / BK) - 1 || kk == (2 * KC / BK) - 1) {
            #pragma unroll
            for (int i = 0; i < 8; i++)
                #pragma unroll
                for (int j = 0; j < 8; j++) {
                    tot[i][j] = __fadd_rn(tot[i][j], acc[i][j]);
                    acc[i][j] = 0.0f;
                }
        }
    }
    // tail panel [640, 700)
    #pragma unroll
    for (int i = 0; i < 8; i++)
        #pragma unroll
        for (int j = 0; j < 8; j++)
            tot[i][j] = __fadd_rn(tot[i][j], acc[i][j]);

    // ---- write out to g_ff[t][b][n] ----
    #pragma unroll
    for (int i = 0; i < 8; i++) {
        int rloc = (i < 4) ? (ty * 4 + i) : (64 + ty * 4 + i - 4);
        int r = row0 + rloc;
        int b = r / TT;
        int t = r % TT;
        size_t base = (size_t)t * BB * NN + (size_t)b * NN;
        #pragma unroll
        for (int q = 0; q < 2; q++) {
            int n = col0 + (q ? (64 + tx * 4) : (tx * 4));
            float4 v;
            v.x = tot[i][q * 4 + 0]; v.y = tot[i][q * 4 + 1];
            v.z = tot[i][q * 4 + 2]; v.w = tot[i][q * 4 + 3];
            if (n + 4 <= NN) {
                *(float4*)&g_ff[base + n] = v;
            } else {
                if (n + 0 < NN) g_ff[base + n + 0] = v.x;
                if (n + 1 < NN) g_ff[base + n + 1] = v.y;
                if (n + 2 < NN) g_ff[base + n + 2] = v.z;
                if (n + 3 < NN) g_ff[base + n + 3] = v.w;
            }
        }
    }
}

// ---------------------------------------------------------------------------
// Spike compaction: one warp per batch row; ordered per-(b,panel) index lists.
// ---------------------------------------------------------------------------
__global__ __launch_bounds__(32)
void compact_kernel(int t) {
    const int b    = blockIdx.x;
    const int lane = threadIdx.x;
    const float* __restrict__ spk = ((t & 1) ? g_spkB : g_spkA) + (size_t)b * NN;

    int cnt = 0;
    for (int j0 = 0; j0 < NN; j0 += 32) {
        if (j0 > 0 && (j0 % KC) == 0) {
            if (lane == 0) g_cnt[b * NPANEL + (j0 / KC) - 1] = cnt;
            cnt = 0;
        }
        int p = j0 / KC; if (p > 6) p = 6;
        int j = j0 + lane;
        float s = (j < NN) ? spk[j] : 0.0f;
        unsigned m = __ballot_sync(0xffffffffu, s != 0.0f);
        int pre = __popc(m & ((1u << lane) - 1u));
        if (s != 0.0f) g_idx[(b * NPANEL + p) * KC + cnt + pre] = j;
        cnt += __popc(m);
    }
    if (lane == 0) g_cnt[b * NPANEL + 6] = cnt;
}

// ---------------------------------------------------------------------------
// Sparse step (unchanged from R13): bit-exact vs dense chain since spk in {0,1}.
// ---------------------------------------------------------------------------
__global__ __launch_bounds__(128)
void sparse_step_kernel(const float* __restrict__ Wrec, float* __restrict__ out, int t) {
    const int b    = blockIdx.y;
    const int col0 = blockIdx.x * 512 + threadIdx.x * 4;
    if (col0 >= NN) return;

    const float* __restrict__ spk_in  = (t & 1) ? g_spkB : g_spkA;
    float* __restrict__       spk_out = (t & 1) ? g_spkA : g_spkB;

    float4 tot = {0.f, 0.f, 0.f, 0.f};

    #pragma unroll 1
    for (int p = 0; p < NPANEL; p++) {
        const int cnt = g_cnt[b * NPANEL + p];
        const int* __restrict__ lst = &g_idx[(b * NPANEL + p) * KC];
        float4 acc = {0.f, 0.f, 0.f, 0.f};
        #pragma unroll 4
        for (int i = 0; i < cnt; i++) {
            int j = lst[i];
            float4 w = *(const float4*)&Wrec[(size_t)j * NN + col0];
            acc.x = __fadd_rn(acc.x, w.x);
            acc.y = __fadd_rn(acc.y, w.y);
            acc.z = __fadd_rn(acc.z, w.z);
            acc.w = __fadd_rn(acc.w, w.w);
        }
        tot.x = __fadd_rn(tot.x, acc.x);
        tot.y = __fadd_rn(tot.y, acc.y);
        tot.z = __fadd_rn(tot.z, acc.z);
        tot.w = __fadd_rn(tot.w, acc.w);
    }

    const size_t base = (size_t)b * NN + col0;
    float4 ffv = *(const float4*)&g_ff[(size_t)t * BB * NN + base];
    float4 m0  = *(const float4*)&g_mem[base];
    float4 s0  = *(const float4*)&spk_in[base];

    float4 mn, sn;
    {
        float cur, t1, t2, t3;
        cur = __fadd_rn(ffv.x, tot.x); t1 = __fmul_rn(TAU, m0.x); t2 = __fsub_rn(1.0f, s0.x);
        t3 = __fmul_rn(t1, t2); mn.x = __fadd_rn(t3, cur); sn.x = (mn.x >= VTH) ? 1.0f : 0.0f;
        cur = __fadd_rn(ffv.y, tot.y); t1 = __fmul_rn(TAU, m0.y); t2 = __fsub_rn(1.0f, s0.y);
        t3 = __fmul_rn(t1, t2); mn.y = __fadd_rn(t3, cur); sn.y = (mn.y >= VTH) ? 1.0f : 0.0f;
        cur = __fadd_rn(ffv.z, tot.z); t1 = __fmul_rn(TAU, m0.z); t2 = __fsub_rn(1.0f, s0.z);
        t3 = __fmul_rn(t1, t2); mn.z = __fadd_rn(t3, cur); sn.z = (mn.z >= VTH) ? 1.0f : 0.0f;
        cur = __fadd_rn(ffv.w, tot.w); t1 = __fmul_rn(TAU, m0.w); t2 = __fsub_rn(1.0f, s0.w);
        t3 = __fmul_rn(t1, t2); mn.w = __fadd_rn(t3, cur); sn.w = (mn.w >= VTH) ? 1.0f : 0.0f;
    }

    *(float4*)&g_mem[base]   = mn;
    *(float4*)&spk_out[base] = sn;

    if (col0 >= NN - NOUT) {
        *(float4*)&out[((size_t)b * TT + t) * NOUT + (col0 - (NN - NOUT))] = sn;
    }
}

// ---------------------------------------------------------------------------
extern "C" void kernel_launch(void* const* d_in, const int* in_sizes, int n_in,
                              void* d_out, int out_size) {
    const float* x  = nullptr;
    const float* W1 = nullptr;
    const float* Wr = nullptr;
    for (int i = 0; i < n_in; i++) {
        if (in_sizes[i] == ROWS * N_IN)      x  = (const float*)d_in[i];
        else if (in_sizes[i] == NN * N_IN)   W1 = (const float*)d_in[i];
        else if (in_sizes[i] == NN * NN)     Wr = (const float*)d_in[i];
    }
    float* out = (float*)d_out;                // [256, 100, 20]

    {
        int total = BB * NN;
        int threads = 256;
        int blocks = (total + threads - 1) / threads;
        zero_state_kernel<<<blocks, threads>>>();
    }

    {
        dim3 grid((NN + BN - 1) / BN, ROWS / BM);  // (17, 200)
        ff_gemm_kernel<<<grid, 256>>>(x, W1);
    }

    {
        dim3 sgrid(5, BB);                     // 5 column-chunks x 256 batches
        for (int t = 0; t < TT; t++) {
            compact_kernel<<<BB, 32>>>(t);
            sparse_step_kernel<<<sgrid, 128>>>(Wr, out, t);
        }
    }
}

// round 16
// speedup vs baseline: 5.1807x; 1.8543x over previous
#include <cuda_runtime.h>

#define N_IN  700
#define NN    2068     // N_HIDDEN + N_OUT
#define NOUT  20
#define BB    256
#define TT    100
#define TAU   0.6f
#define VTH   1.0f

#define ROWS  (BB * TT)        // 25600 rows of the ff GEMM

// Eigen gebp kc blocking (confirmed bit-exact): kc = 320.
#define KC        320
#define NPANEL    7

// ff GEMM tiling
#define BM 128
#define BN 128
#define BK 16
#define FF_NK 44               // ceil(700/16) -> k padded to 704 with zeros

// Scratch (device globals: allocation-free rule)
__device__ float g_ff[(size_t)TT * BB * NN];   // [T][B][N]  ~212 MB

// ---------------------------------------------------------------------------
// Phase 1: ff[t][b][n] = sum_i x[b][t][i] * W1[n][i]     (GEMM-NT)
// Per-element: strictly ascending-k FMA chain, panel breaks after k=320, 640:
//   tot = ((P0 + P1) + P2)  with separately-rounded adds  (Eigen gebp kc=320).
// (unchanged from R15 — bit-exact verified)
// ---------------------------------------------------------------------------
__global__ __launch_bounds__(256, 1)
void ff_gemm_kernel(const float* __restrict__ X, const float* __restrict__ W1) {
    __shared__ float As[2][BK][BM];
    __shared__ float Bs[2][BK][BN];

    const int col0 = blockIdx.x * BN;   // n
    const int row0 = blockIdx.y * BM;   // r = b*TT + t
    const int tid  = threadIdx.x;
    const int tx   = tid & 15;          // n-dim
    const int ty   = tid >> 4;          // r-dim

    const int lrow = tid & 127;
    const int lkq  = (tid >> 7) * 4;

    float4 stA0, stA1, stB0, stB1;

    {
        const int gr = row0 + lrow;
        const int gn = col0 + lrow;
        #pragma unroll
        for (int s = 0; s < 2; s++) {
            int kq = lkq + s * 8;
            int gk = kq;
            float4 va = {0.f,0.f,0.f,0.f}, vb = {0.f,0.f,0.f,0.f};
            if (gk + 4 <= N_IN) {
                va = *(const float4*)&X[(size_t)gr * N_IN + gk];
                if (gn < NN) vb = *(const float4*)&W1[(size_t)gn * N_IN + gk];
            }
            As[0][kq + 0][lrow] = va.x; As[0][kq + 1][lrow] = va.y;
            As[0][kq + 2][lrow] = va.z; As[0][kq + 3][lrow] = va.w;
            Bs[0][kq + 0][lrow] = vb.x; Bs[0][kq + 1][lrow] = vb.y;
            Bs[0][kq + 2][lrow] = vb.z; Bs[0][kq + 3][lrow] = vb.w;
        }
    }
    __syncthreads();

    float acc[8][8] = {};
    float tot[8][8] = {};

    int buf = 0;
    for (int kk = 0; kk < FF_NK; kk++) {
        const bool have_next = (kk + 1 < FF_NK);
        if (have_next) {
            const int k0 = (kk + 1) * BK;
            const int gr = row0 + lrow;
            const int gn = col0 + lrow;
            {
                int gk = k0 + lkq;
                float4 va = {0.f,0.f,0.f,0.f}, vb = {0.f,0.f,0.f,0.f};
                if (gk + 4 <= N_IN) {
                    va = *(const float4*)&X[(size_t)gr * N_IN + gk];
                    if (gn < NN) vb = *(const float4*)&W1[(size_t)gn * N_IN + gk];
                } else {
                    if (gk + 0 < N_IN) { va.x = X[(size_t)gr * N_IN + gk + 0]; if (gn < NN) vb.x = W1[(size_t)gn * N_IN + gk + 0]; }
                    if (gk + 1 < N_IN) { va.y = X[(size_t)gr * N_IN + gk + 1]; if (gn < NN) vb.y = W1[(size_t)gn * N_IN + gk + 1]; }
                    if (gk + 2 < N_IN) { va.z = X[(size_t)gr * N_IN + gk + 2]; if (gn < NN) vb.z = W1[(size_t)gn * N_IN + gk + 2]; }
                    if (gk + 3 < N_IN) { va.w = X[(size_t)gr * N_IN + gk + 3]; if (gn < NN) vb.w = W1[(size_t)gn * N_IN + gk + 3]; }
                }
                stA0 = va; stB0 = vb;
            }
            {
                int gk = k0 + lkq + 8;
                float4 va = {0.f,0.f,0.f,0.f}, vb = {0.f,0.f,0.f,0.f};
                if (gk + 4 <= N_IN) {
                    va = *(const float4*)&X[(size_t)gr * N_IN + gk];
                    if (gn < NN) vb = *(const float4*)&W1[(size_t)gn * N_IN + gk];
                } else {
                    if (gk + 0 < N_IN) { va.x = X[(size_t)gr * N_IN + gk + 0]; if (gn < NN) vb.x = W1[(size_t)gn * N_IN + gk + 0]; }
                    if (gk + 1 < N_IN) { va.y = X[(size_t)gr * N_IN + gk + 1]; if (gn < NN) vb.y = W1[(size_t)gn * N_IN + gk + 1]; }
                    if (gk + 2 < N_IN) { va.z = X[(size_t)gr * N_IN + gk + 2]; if (gn < NN) vb.z = W1[(size_t)gn * N_IN + gk + 2]; }
                    if (gk + 3 < N_IN) { va.w = X[(size_t)gr * N_IN + gk + 3]; if (gn < NN) vb.w = W1[(size_t)gn * N_IN + gk + 3]; }
                }
                stA1 = va; stB1 = vb;
            }
        }

        #pragma unroll
        for (int k = 0; k < BK; k++) {
            float4 a0 = *(const float4*)&As[buf][k][ty * 4];
            float4 a1 = *(const float4*)&As[buf][k][64 + ty * 4];
            float4 b0 = *(const float4*)&Bs[buf][k][tx * 4];
            float4 b1 = *(const float4*)&Bs[buf][k][64 + tx * 4];
            float ar[8] = {a0.x, a0.y, a0.z, a0.w, a1.x, a1.y, a1.z, a1.w};
            float br[8] = {b0.x, b0.y, b0.z, b0.w, b1.x, b1.y, b1.z, b1.w};
            #pragma unroll
            for (int i = 0; i < 8; i++)
                #pragma unroll
                for (int j = 0; j < 8; j++)
                    acc[i][j] = __fmaf_rn(ar[i], br[j], acc[i][j]);
        }

        if (have_next) {
            int nb = buf ^ 1;
            As[nb][lkq + 0][lrow] = stA0.x; As[nb][lkq + 1][lrow] = stA0.y;
            As[nb][lkq + 2][lrow] = stA0.z; As[nb][lkq + 3][lrow] = stA0.w;
            As[nb][lkq + 8][lrow] = stA1.x; As[nb][lkq + 9][lrow] = stA1.y;
            As[nb][lkq +10][lrow] = stA1.z; As[nb][lkq +11][lrow] = stA1.w;
            Bs[nb][lkq + 0][lrow] = stB0.x; Bs[nb][lkq + 1][lrow] = stB0.y;
            Bs[nb][lkq + 2][lrow] = stB0.z; Bs[nb][lkq + 3][lrow] = stB0.w;
            Bs[nb][lkq + 8][lrow] = stB1.x; Bs[nb][lkq + 9][lrow] = stB1.y;
            Bs[nb][lkq +10][lrow] = stB1.z; Bs[nb][lkq +11][lrow] = stB1.w;
            __syncthreads();
            buf = nb;
        }

        if (kk == (KC / BK) - 1 || kk == (2 * KC / BK) - 1) {
            #pragma unroll
            for (int i = 0; i < 8; i++)
                #pragma unroll
                for (int j = 0; j < 8; j++) {
                    tot[i][j] = __fadd_rn(tot[i][j], acc[i][j]);
                    acc[i][j] = 0.0f;
                }
        }
    }
    #pragma unroll
    for (int i = 0; i < 8; i++)
        #pragma unroll
        for (int j = 0; j < 8; j++)
            tot[i][j] = __fadd_rn(tot[i][j], acc[i][j]);

    #pragma unroll
    for (int i = 0; i < 8; i++) {
        int rloc = (i < 4) ? (ty * 4 + i) : (64 + ty * 4 + i - 4);
        int r = row0 + rloc;
        int b = r / TT;
        int t = r % TT;
        size_t base = (size_t)t * BB * NN + (size_t)b * NN;
        #pragma unroll
        for (int q = 0; q < 2; q++) {
            int n = col0 + (q ? (64 + tx * 4) : (tx * 4));
            float4 v;
            v.x = tot[i][q * 4 + 0]; v.y = tot[i][q * 4 + 1];
            v.z = tot[i][q * 4 + 2]; v.w = tot[i][q * 4 + 3];
            if (n + 4 <= NN) {
                *(float4*)&g_ff[base + n] = v;
            } else {
                if (n + 0 < NN) g_ff[base + n + 0] = v.x;
                if (n + 1 < NN) g_ff[base + n + 1] = v.y;
                if (n + 2 < NN) g_ff[base + n + 2] = v.z;
                if (n + 3 < NN) g_ff[base + n + 3] = v.w;
            }
        }
    }
}

// ---------------------------------------------------------------------------
// Phase 2: persistent per-batch RSNN. One block = one batch element, runs all
// 100 timesteps. mem lives in registers, spikes + compacted per-panel index
// lists in smem. Bit-exact vs dense chain (spk in {0,1}; same ascending-j
// order within kc=320 panels; C += panel separately rounded; LIF per-op rn).
//
// Column ownership (256 threads): thread owns float4 cols {4t, 1024+4t},
// and threads 0..4 additionally own the tail float4 {2048+4t} (cols 2048-2067).
// ---------------------------------------------------------------------------
__global__ __launch_bounds__(256, 2)
void rsnn_persistent_kernel(const float* __restrict__ Wrec, float* __restrict__ out) {
    __shared__ float s_spk[NN];           // spike flags for current step input
    __shared__ int   s_idx[NPANEL][KC];   // compacted ascending indices per panel
    __shared__ int   s_cnt[NPANEL];

    const int b    = blockIdx.x;
    const int tid  = threadIdx.x;
    const int wid  = tid >> 5;
    const int lane = tid & 31;

    const int c0 = 4 * tid;               // 0..1023
    const int c1 = 1024 + 4 * tid;        // 1024..2047
    const bool has_tail = (tid < 5);
    const int ct = 2048 + 4 * tid;        // 2048..2067 (tid<5)

    // mem state in registers; prev-spike state in registers (init 0)
    float4 m0 = {0,0,0,0}, m1 = {0,0,0,0}, mt = {0,0,0,0};
    float4 p0 = {0,0,0,0}, p1 = {0,0,0,0}, pt = {0,0,0,0};

    // init spike flags to zero (t=0 input spikes are zero)
    for (int i = tid; i < NN; i += 256) s_spk[i] = 0.0f;
    __syncthreads();

    const float* __restrict__ ff_b = g_ff + (size_t)b * NN;   // + t*BB*NN per step
    float* __restrict__ out_b = out + (size_t)b * TT * NOUT;

    for (int t = 0; t < TT; t++) {
        // ---- compact: warp w handles panel w (ascending j, ballot order) ----
        if (wid < NPANEL) {
            const int base = wid * KC;
            const int len  = (wid == NPANEL - 1) ? (NN - (NPANEL - 1) * KC) : KC;  // 148 or 320
            int cnt = 0;
            for (int r = 0; r < len; r += 32) {
                int off = r + lane;
                float s = (off < len) ? s_spk[base + off] : 0.0f;
                unsigned m = __ballot_sync(0xffffffffu, s != 0.0f);
                int pre = __popc(m & ((1u << lane) - 1u));
                if (s != 0.0f) s_idx[wid][cnt + pre] = base + off;
                cnt += __popc(m);
            }
            if (lane == 0) s_cnt[wid] = cnt;
        }
        __syncthreads();

        // ---- gather: per owned column, ascending j within panel, C += panel ----
        float4 t0 = {0,0,0,0}, t1 = {0,0,0,0}, tt = {0,0,0,0};
        #pragma unroll 1
        for (int p = 0; p < NPANEL; p++) {
            const int cnt = s_cnt[p];
            float4 a0 = {0,0,0,0}, a1 = {0,0,0,0}, at = {0,0,0,0};
            #pragma unroll 4
            for (int i = 0; i < cnt; i++) {
                const int j = s_idx[p][i];
                const float* __restrict__ row = Wrec + (size_t)j * NN;
                float4 w0 = *(const float4*)&row[c0];
                float4 w1 = *(const float4*)&row[c1];
                a0.x = __fadd_rn(a0.x, w0.x); a0.y = __fadd_rn(a0.y, w0.y);
                a0.z = __fadd_rn(a0.z, w0.z); a0.w = __fadd_rn(a0.w, w0.w);
                a1.x = __fadd_rn(a1.x, w1.x); a1.y = __fadd_rn(a1.y, w1.y);
                a1.z = __fadd_rn(a1.z, w1.z); a1.w = __fadd_rn(a1.w, w1.w);
                if (has_tail) {
                    float4 wt = *(const float4*)&row[ct];
                    at.x = __fadd_rn(at.x, wt.x); at.y = __fadd_rn(at.y, wt.y);
                    at.z = __fadd_rn(at.z, wt.z); at.w = __fadd_rn(at.w, wt.w);
                }
            }
            t0.x = __fadd_rn(t0.x, a0.x); t0.y = __fadd_rn(t0.y, a0.y);
            t0.z = __fadd_rn(t0.z, a0.z); t0.w = __fadd_rn(t0.w, a0.w);
            t1.x = __fadd_rn(t1.x, a1.x); t1.y = __fadd_rn(t1.y, a1.y);
            t1.z = __fadd_rn(t1.z, a1.z); t1.w = __fadd_rn(t1.w, a1.w);
            if (has_tail) {
                tt.x = __fadd_rn(tt.x, at.x); tt.y = __fadd_rn(tt.y, at.y);
                tt.z = __fadd_rn(tt.z, at.z); tt.w = __fadd_rn(tt.w, at.w);
            }
        }

        // ---- LIF update (per-op rounding), spike, state, output ----
        const float* __restrict__ ff_t = ff_b + (size_t)t * BB * NN;
        float4 f0 = *(const float4*)&ff_t[c0];
        float4 f1 = *(const float4*)&ff_t[c1];

        float4 sn0, sn1, snt;
        {
            float cur, x1, x2, x3;
            cur = __fadd_rn(f0.x, t0.x); x1 = __fmul_rn(TAU, m0.x); x2 = __fsub_rn(1.0f, p0.x);
            x3 = __fmul_rn(x1, x2); m0.x = __fadd_rn(x3, cur); sn0.x = (m0.x >= VTH) ? 1.0f : 0.0f;
            cur = __fadd_rn(f0.y, t0.y); x1 = __fmul_rn(TAU, m0.y); x2 = __fsub_rn(1.0f, p0.y);
            x3 = __fmul_rn(x1, x2); m0.y = __fadd_rn(x3, cur); sn0.y = (m0.y >= VTH) ? 1.0f : 0.0f;
            cur = __fadd_rn(f0.z, t0.z); x1 = __fmul_rn(TAU, m0.z); x2 = __fsub_rn(1.0f, p0.z);
            x3 = __fmul_rn(x1, x2); m0.z = __fadd_rn(x3, cur); sn0.z = (m0.z >= VTH) ? 1.0f : 0.0f;
            cur = __fadd_rn(f0.w, t0.w); x1 = __fmul_rn(TAU, m0.w); x2 = __fsub_rn(1.0f, p0.w);
            x3 = __fmul_rn(x1, x2); m0.w = __fadd_rn(x3, cur); sn0.w = (m0.w >= VTH) ? 1.0f : 0.0f;

            cur = __fadd_rn(f1.x, t1.x); x1 = __fmul_rn(TAU, m1.x); x2 = __fsub_rn(1.0f, p1.x);
            x3 = __fmul_rn(x1, x2); m1.x = __fadd_rn(x3, cur); sn1.x = (m1.x >= VTH) ? 1.0f : 0.0f;
            cur = __fadd_rn(f1.y, t1.y); x1 = __fmul_rn(TAU, m1.y); x2 = __fsub_rn(1.0f, p1.y);
            x3 = __fmul_rn(x1, x2); m1.y = __fadd_rn(x3, cur); sn1.y = (m1.y >= VTH) ? 1.0f : 0.0f;
            cur = __fadd_rn(f1.z, t1.z); x1 = __fmul_rn(TAU, m1.z); x2 = __fsub_rn(1.0f, p1.z);
            x3 = __fmul_rn(x1, x2); m1.z = __fadd_rn(x3, cur); sn1.z = (m1.z >= VTH) ? 1.0f : 0.0f;
            cur = __fadd_rn(f1.w, t1.w); x1 = __fmul_rn(TAU, m1.w); x2 = __fsub_rn(1.0f, p1.w);
            x3 = __fmul_rn(x1, x2); m1.w = __fadd_rn(x3, cur); sn1.w = (m1.w >= VTH) ? 1.0f : 0.0f;
        }
        if (has_tail) {
            float4 ft = *(const float4*)&ff_t[ct];
            float cur, x1, x2, x3;
            cur = __fadd_rn(ft.x, tt.x); x1 = __fmul_rn(TAU, mt.x); x2 = __fsub_rn(1.0f, pt.x);
            x3 = __fmul_rn(x1, x2); mt.x = __fadd_rn(x3, cur); snt.x = (mt.x >= VTH) ? 1.0f : 0.0f;
            cur = __fadd_rn(ft.y, tt.y); x1 = __fmul_rn(TAU, mt.y); x2 = __fsub_rn(1.0f, pt.y);
            x3 = __fmul_rn(x1, x2); mt.y = __fadd_rn(x3, cur); snt.y = (mt.y >= VTH) ? 1.0f : 0.0f;
            cur = __fadd_rn(ft.z, tt.z); x1 = __fmul_rn(TAU, mt.z); x2 = __fsub_rn(1.0f, pt.z);
            x3 = __fmul_rn(x1, x2); mt.z = __fadd_rn(x3, cur); snt.z = (mt.z >= VTH) ? 1.0f : 0.0f;
            cur = __fadd_rn(ft.w, tt.w); x1 = __fmul_rn(TAU, mt.w); x2 = __fsub_rn(1.0f, pt.w);
            x3 = __fmul_rn(x1, x2); mt.w = __fadd_rn(x3, cur); snt.w = (mt.w >= VTH) ? 1.0f : 0.0f;

            // output cols 2048..2067 -> out[b][t][4*tid .. 4*tid+3]
            *(float4*)&out_b[(size_t)t * NOUT + 4 * tid] = snt;
        }

        // ---- publish new spike flags for next step's compaction ----
        *(float4*)&s_spk[c0] = sn0;
        *(float4*)&s_spk[c1] = sn1;
        if (has_tail) *(float4*)&s_spk[ct] = snt;
        p0 = sn0; p1 = sn1; if (has_tail) pt = snt;

        __syncthreads();   // flags complete + gather done before next compaction
    }
}

// ---------------------------------------------------------------------------
extern "C" void kernel_launch(void* const* d_in, const int* in_sizes, int n_in,
                              void* d_out, int out_size) {
    const float* x  = nullptr;
    const float* W1 = nullptr;
    const float* Wr = nullptr;
    for (int i = 0; i < n_in; i++) {
        if (in_sizes[i] == ROWS * N_IN)      x  = (const float*)d_in[i];
        else if (in_sizes[i] == NN * N_IN)   W1 = (const float*)d_in[i];
        else if (in_sizes[i] == NN * NN)     Wr = (const float*)d_in[i];
    }
    float* out = (float*)d_out;                // [256, 100, 20]

    {
        dim3 grid((NN + BN - 1) / BN, ROWS / BM);  // (17, 200)
        ff_gemm_kernel<<<grid, 256>>>(x, W1);
    }

    rsnn_persistent_kernel<<<BB, 256>>>(Wr, out);
}